// round 11
// baseline (speedup 1.0000x reference)
#include <cuda_runtime.h>
#include <cuda_fp16.h>

typedef unsigned int u32;
typedef unsigned long long u64;

#define NB 64
#define CIN 128
#define COUT 128
#define TT 128
#define JJ 25
#define NTOT 3328            // 128 t * 26 cols (k=25 is zero pad)

// ---------------- gmem scratch ----------------
__device__ __half gXh[NB * CIN * NTOT];   // 54.5 MB
__device__ __half gXl[NB * CIN * NTOT];   // 54.5 MB
__device__ float g_xt_mean[NB * CIN * JJ];
__device__ float g_E[NB * JJ * JJ];
__device__ float g_csf[NB * JJ];

// ---------------- helpers ----------------
__device__ __forceinline__ u64 pack2(float lo, float hi) {
    u64 r; asm("mov.b64 %0, {%1,%2};" : "=l"(r) : "f"(lo), "f"(hi)); return r;
}
__device__ __forceinline__ void unpack2(u64 v, float& lo, float& hi) {
    asm("mov.b64 {%0,%1}, %2;" : "=f"(lo), "=f"(hi) : "l"(v));
}
__device__ __forceinline__ u64 ffma2(u64 a, u64 b, u64 c) {
    u64 d; asm("fma.rn.f32x2 %0, %1, %2, %3;" : "=l"(d) : "l"(a), "l"(b), "l"(c)); return d;
}
__device__ __forceinline__ u32 smem_u32(const void* p) {
    u32 a; asm("{ .reg .u64 t; cvta.to.shared.u64 t, %1; cvt.u32.u64 %0, t; }" : "=r"(a) : "l"(p));
    return a;
}
__device__ __forceinline__ void ldsm_x4(u32* r, u32 addr) {
    asm volatile("ldmatrix.sync.aligned.m8n8.x4.shared.b16 {%0,%1,%2,%3}, [%4];"
        : "=r"(r[0]), "=r"(r[1]), "=r"(r[2]), "=r"(r[3]) : "r"(addr) : "memory");
}
__device__ __forceinline__ void ldsm_x4t(u32* r, u32 addr) {
    asm volatile("ldmatrix.sync.aligned.m8n8.x4.trans.shared.b16 {%0,%1,%2,%3}, [%4];"
        : "=r"(r[0]), "=r"(r[1]), "=r"(r[2]), "=r"(r[3]) : "r"(addr) : "memory");
}
__device__ __forceinline__ void ldsm_x2t(u32* r, u32 addr) {
    asm volatile("ldmatrix.sync.aligned.m8n8.x2.trans.shared.b16 {%0,%1}, [%2];"
        : "=r"(r[0]), "=r"(r[1]) : "r"(addr) : "memory");
}
__device__ __forceinline__ void mma_fp16(float* d, const u32* a, const u32* b) {
    asm volatile("mma.sync.aligned.m16n8k16.row.col.f32.f16.f16.f32 "
        "{%0,%1,%2,%3}, {%4,%5,%6,%7}, {%8,%9}, {%0,%1,%2,%3};"
        : "+f"(d[0]), "+f"(d[1]), "+f"(d[2]), "+f"(d[3])
        : "r"(a[0]), "r"(a[1]), "r"(a[2]), "r"(a[3]), "r"(b[0]), "r"(b[1]));
}
__device__ __forceinline__ void cp4(u32 dst, const void* src) {
    asm volatile("cp.async.ca.shared.global [%0], [%1], 4;" :: "r"(dst), "l"(src) : "memory");
}
__device__ __forceinline__ void cp8(u32 dst, const void* src) {
    asm volatile("cp.async.ca.shared.global [%0], [%1], 8;" :: "r"(dst), "l"(src) : "memory");
}
#define CP_COMMIT() asm volatile("cp.async.commit_group;" ::: "memory")
#define CP_WAIT1()  asm volatile("cp.async.wait_group 1;" ::: "memory")
#define CP_WAITALL() asm volatile("cp.async.wait_group 0;" ::: "memory")

__device__ __forceinline__ u32 packh(float a, float b) {
    __half h0 = __float2half_rn(a), h1 = __float2half_rn(b);
    return (u32)__half_as_ushort(h0) | ((u32)__half_as_ushort(h1) << 16);
}

// ---------------- K1: temporal mean ----------------
__global__ void k1_mean(const float* __restrict__ x) {
    int b = blockIdx.y;
    int c = blockIdx.x * 8 + (threadIdx.x >> 5);
    int j = threadIdx.x & 31;
    if (j >= JJ) return;
    const float* p = x + ((size_t)(b * CIN + c) * TT) * JJ + j;
    float a0 = 0.f, a1 = 0.f, a2 = 0.f, a3 = 0.f;
    float a4 = 0.f, a5 = 0.f, a6 = 0.f, a7 = 0.f;
#pragma unroll 4
    for (int t = 0; t < TT; t += 8) {
        a0 += p[t * JJ];       a1 += p[(t + 1) * JJ];
        a2 += p[(t + 2) * JJ]; a3 += p[(t + 3) * JJ];
        a4 += p[(t + 4) * JJ]; a5 += p[(t + 5) * JJ];
        a6 += p[(t + 6) * JJ]; a7 += p[(t + 7) * JJ];
    }
    g_xt_mean[(b * CIN + c) * JJ + j] =
        ((a0 + a1) + (a2 + a3) + ((a4 + a5) + (a6 + a7))) * (1.0f / TT);
}

// ---------------- K2: per-batch attention -> E[b], csf[b] ----------------
__global__ void k2_attn(const float* __restrict__ adj,
                        const float* __restrict__ Wk, const float* __restrict__ bk,
                        const float* __restrict__ Wq, const float* __restrict__ bq,
                        const float* __restrict__ alphaPtr) {
    int b = blockIdx.x;
    int tid = threadIdx.x;  // 128
    __shared__ float xt[CIN * 26];
    __shared__ float skk[COUT * 26];
    __shared__ float sqq[COUT * 26];
    __shared__ float sdyn[JJ * 26];

    for (int i = tid; i < CIN * JJ; i += 128) {
        int c = i / JJ, j = i - c * JJ;
        xt[c * 26 + j] = g_xt_mean[b * CIN * JJ + i];
    }
    __syncthreads();
    {
        int o = tid;
        const float4* wk4 = (const float4*)(Wk + o * CIN);
        const float4* wq4 = (const float4*)(Wq + o * CIN);
        float ak[JJ], aq[JJ];
#pragma unroll
        for (int j = 0; j < JJ; j++) { ak[j] = 0.f; aq[j] = 0.f; }
#pragma unroll 4
        for (int c4 = 0; c4 < CIN / 4; ++c4) {
            float4 wk = wk4[c4], wq = wq4[c4];
            const float* x0 = &xt[(c4 * 4) * 26];
#pragma unroll
            for (int j = 0; j < JJ; j++) {
                float v0 = x0[j], v1 = x0[26 + j], v2 = x0[52 + j], v3 = x0[78 + j];
                float a = ak[j], q = aq[j];
                a = fmaf(wk.x, v0, a); q = fmaf(wq.x, v0, q);
                a = fmaf(wk.y, v1, a); q = fmaf(wq.y, v1, q);
                a = fmaf(wk.z, v2, a); q = fmaf(wq.z, v2, q);
                a = fmaf(wk.w, v3, a); q = fmaf(wq.w, v3, q);
                ak[j] = a; aq[j] = q;
            }
        }
        float bko = bk[o], bqo = bq[o];
#pragma unroll
        for (int j = 0; j < JJ; j++) { skk[o * 26 + j] = ak[j] + bko; sqq[o * 26 + j] = aq[j] + bqo; }
    }
    __syncthreads();
    const float inv_scale = 0.08838834764831843f;
    for (int i = tid; i < JJ * JJ; i += 128) {
        int j = i / JJ, k = i - j * JJ;
        float acc = 0.f;
        for (int o = 0; o < COUT; o++) acc = fmaf(sqq[o * 26 + j], skk[o * 26 + k], acc);
        sdyn[j * 26 + k] = acc * inv_scale;
    }
    __syncthreads();
    if (tid < JJ) {
        int j = tid;
        float m = -1e30f;
#pragma unroll
        for (int k = 0; k < JJ; k++) m = fmaxf(m, sdyn[j * 26 + k]);
        float e[JJ]; float s = 0.f;
#pragma unroll
        for (int k = 0; k < JJ; k++) { e[k] = expf(sdyn[j * 26 + k] - m); s += e[k]; }
        float inv = 1.0f / s;
#pragma unroll
        for (int k = 0; k < JJ; k++) sdyn[j * 26 + k] = e[k] * inv;
    }
    __syncthreads();
    float alpha = alphaPtr[0];
    for (int i = tid; i < JJ * JJ; i += 128) {
        int j = i / JJ, k = i - j * JJ;
        float acc = 0.f;
#pragma unroll
        for (int m2 = 0; m2 < JJ; m2++) acc = fmaf(adj[j * JJ + m2], sdyn[m2 * 26 + k], acc);
        g_E[b * JJ * JJ + i] = adj[j * JJ + k] + alpha * acc;
    }
    if (tid < JJ) {
        int k = tid;
        float acc = 0.f;
#pragma unroll
        for (int j = 0; j < JJ; j++) acc += sdyn[j * 26 + k];
        g_csf[b * JJ + k] = 1.0f + alpha * acc;
    }
}

// ---------------- KM: mix  Xmix = X * E  -> fp16 hi/lo scratch ----------------
// grid (32 slabs of 4t, 64 b), 256 threads. smem: Es 2624B + raw 51712B = 54336
#define KM_RAW_OFF 2624
#define KM_SMEM 54336

__device__ __forceinline__ void km_store_row(const u64* z, int b, int c, int t) {
    size_t base = (size_t)(b * CIN + c) * NTOT + (size_t)t * 26;
    u32* ph = (u32*)(gXh + base);
    u32* pl = (u32*)(gXl + base);
#pragma unroll
    for (int q = 0; q < 13; ++q) {
        float f0, f1; unpack2(z[q], f0, f1);
        __half h0 = __float2half_rn(f0), h1 = __float2half_rn(f1);
        ph[q] = (u32)__half_as_ushort(h0) | ((u32)__half_as_ushort(h1) << 16);
        pl[q] = packh(f0 - __half2float(h0), f1 - __half2float(h1));
    }
}

__global__ void __launch_bounds__(256)
km_mix(const float* __restrict__ x) {
    extern __shared__ char smq[];
    float* Es  = (float*)smq;                 // [25][26], col 25 zero
    float* raw = (float*)(smq + KM_RAW_OFF);  // [128 c][101] (4t*25 + pad)
    u32 sb = smem_u32(smq);
    int tid = threadIdx.x;
    int slab = blockIdx.x, b = blockIdx.y;
    int t0 = slab * 4;

    const float* xb = x + (size_t)b * 409600 + (size_t)t0 * 25;
#pragma unroll
    for (int i = 0; i < 50; ++i) {
        int flat = i * 256 + tid;
        int c = flat / 100, col = flat - 100 * c;
        cp4(sb + KM_RAW_OFF + (u32)((c * 101 + col) * 4), xb + (size_t)c * 3200 + col);
    }
    CP_COMMIT();
    for (int i = tid; i < 650; i += 256) {
        int j = i / 26, k = i - 26 * j;
        Es[i] = (k < JJ) ? g_E[b * 625 + j * 25 + k] : 0.f;
    }
    CP_WAITALL();
    __syncthreads();

    int c0 = tid >> 2, tl0 = tid & 3;
    int r1 = tid + 256;
    int c1 = r1 >> 2, tl1 = r1 & 3;
    const float* xr0 = raw + c0 * 101 + tl0 * 25;
    const float* xr1 = raw + c1 * 101 + tl1 * 25;

    u64 z0[13], z1[13];
    u64 zero = pack2(0.f, 0.f);
#pragma unroll
    for (int q = 0; q < 13; ++q) { z0[q] = zero; z1[q] = zero; }
#pragma unroll
    for (int j = 0; j < JJ; ++j) {
        const u64* er = (const u64*)&Es[j * 26];
        float f0 = xr0[j], f1 = xr1[j];
        u64 p0 = pack2(f0, f0), p1 = pack2(f1, f1);
#pragma unroll
        for (int q = 0; q < 13; ++q) {
            u64 e = er[q];
            z0[q] = ffma2(p0, e, z0[q]);
            z1[q] = ffma2(p1, e, z1[q]);
        }
    }
    km_store_row(z0, b, c0, t0 + tl0);
    km_store_row(z1, b, c1, t0 + tl1);
}

// ---------------- KG: persistent 3-term GEMM + BN + ReLU ----------------
// grid (16 n-groups, 8 b-groups), 256 threads, 1 wave. CTA: A resident,
// loops 8 b * 4 n-stages of 52 cols, 2-stage cp.async double buffer.
#define G_SBN 0
#define G_CSF 2048                 // [8 b][32] floats
#define G_AHI 3072                 // 128*136*2 = 34816
#define G_ALO 37888
#define G_B0  72704                // stage s: BH = G_B0 + s*36864, BL = BH+18432
#define G_D   146432               // 128*53*4 = 27136
#define KG_SMEM 173568
#define BP2 72                     // B pitch (halves): 144B rows, conflict-free
#define DP2 53

__device__ __forceinline__ void kg_issue(u32 sbase, int tid, int bb, int n0, int buf) {
    const __half* srcH = gXh + (size_t)bb * CIN * NTOT + n0;
    const __half* srcL = gXl + (size_t)bb * CIN * NTOT + n0;
    u32 dH = sbase + (u32)G_B0 + (u32)buf * 36864u;
    u32 dL = dH + 18432u;
#pragma unroll
    for (int i = 0; i < 7; ++i) {
        int flat = i * 256 + tid;
        if (flat < 1664) {
            int c = flat / 13, ch = flat - 13 * c;
            cp8(dH + (u32)(c * 144 + ch * 8), srcH + (size_t)c * NTOT + ch * 4);
        }
    }
#pragma unroll
    for (int i = 0; i < 7; ++i) {
        int flat = i * 256 + tid;
        if (flat < 1664) {
            int c = flat / 13, ch = flat - 13 * c;
            cp8(dL + (u32)(c * 144 + ch * 8), srcL + (size_t)c * NTOT + ch * 4);
        }
    }
}

__global__ void __launch_bounds__(256, 1)
kg_gemm(const float* __restrict__ Ws, const float* __restrict__ bs,
        const float* __restrict__ gamma, const float* __restrict__ beta,
        const float* __restrict__ rmean, const float* __restrict__ rvar,
        float* __restrict__ out) {
    extern __shared__ char smq[];
    u32 sbase = smem_u32(smq);
    int tid = threadIdx.x;
    int nb = blockIdx.x, bg = blockIdx.y;

    // prologue: prefetch stage 0 first (overlap with A prep)
    kg_issue(sbase, tid, bg * 8, nb * 208, 0);
    CP_COMMIT();

    // staging: BN table, csf (8 b), A hi/lo
    if (tid < 128) {
        int o = tid;
        float inv = gamma[o] * rsqrtf(rvar[o] + 1e-5f);
        float sh = beta[o] - rmean[o] * inv;
        ((float4*)(smq + G_SBN))[o] = make_float4(inv, sh, bs[o], 0.f);
    }
    {
        float* csf = (float*)(smq + G_CSF);
        for (int i = tid; i < 8 * 32; i += 256) {
            int bi = i >> 5, k = i & 31;
            csf[i] = (k < JJ) ? g_csf[(bg * 8 + bi) * JJ + k] : 0.f;
        }
    }
    {
        __half* ah = (__half*)(smq + G_AHI);
        __half* al = (__half*)(smq + G_ALO);
        for (int i = tid; i < COUT * CIN; i += 256) {
            int o = i >> 7, c = i & 127;
            float v = Ws[i];
            __half hb = __float2half_rn(v);
            ah[o * 136 + c] = hb;
            al[o * 136 + c] = __float2half_rn(v - __half2float(hb));
        }
    }
    __syncthreads();

    int warp = tid >> 5, lane = tid & 31;
    int o0 = warp * 16;
    int gid = lane >> 2, tig = lane & 3;
    u32 arow  = (u32)(o0 + (lane & 15));
    u32 acsel = (u32)((lane >> 4) * 8);
    u32 brow  = (u32)((lane & 7) + ((lane >> 3) & 1) * 8);
    u32 bcsel = (u32)((lane >> 4) * 8);
    u32 brow2 = (u32)(lane & 15);
    int o_a = o0 + gid, o_b = o_a + 8;
    const float4* sbn = (const float4*)(smq + G_SBN);
    const float* csf = (const float*)(smq + G_CSF);
    float* D = (float*)(smq + G_D);

    u32 AbH = sbase + (u32)G_AHI + (arow * 136 + acsel) * 2;
    u32 AbL = sbase + (u32)G_ALO + (arow * 136 + acsel) * 2;

    // persistent Ahi frags (same A for all 32 stages)
    u32 fahi[8][4];
#pragma unroll
    for (int kt = 0; kt < 8; ++kt) ldsm_x4(fahi[kt], AbH + (u32)(kt * 32));

    for (int s = 0; s < 32; ++s) {
        int sb2 = s & 1;
        int bi = s >> 2, ns = s & 3;
        int bb = bg * 8 + bi;
        // prefetch next stage, then ensure current landed
        if (s + 1 < 32) {
            int bn = s + 1;
            kg_issue(sbase, tid, bg * 8 + (bn >> 2), nb * 208 + (bn & 3) * 52, bn & 1);
            CP_COMMIT();
            CP_WAIT1();
        } else {
            CP_WAITALL();
        }
        __syncthreads();   // B[sb2] visible to all

        u32 BH = sbase + (u32)G_B0 + (u32)sb2 * 36864u;
        u32 BL = BH + 18432u;
        u32 BroH  = BH + (brow * BP2 + bcsel) * 2;
        u32 BroL  = BL + (brow * BP2 + bcsel) * 2;
        u32 Bro2H = BH + (brow2 * BP2 + 48u) * 2;
        u32 Bro2L = BL + (brow2 * BP2 + 48u) * 2;

        float acc[7][4];
#pragma unroll
        for (int nt = 0; nt < 7; ++nt)
#pragma unroll
            for (int r = 0; r < 4; ++r) acc[nt][r] = 0.f;

        u32 bhi[2][14], blo[14], alo[4];
#define LDBHI(pb, kt) do {                                                  \
    u32 kb = (u32)((kt) * 16 * BP2 * 2);                                    \
    ldsm_x4t(&bhi[pb][0],  BroH + kb);                                      \
    ldsm_x4t(&bhi[pb][4],  BroH + kb + 32u);                                \
    ldsm_x4t(&bhi[pb][8],  BroH + kb + 64u);                                \
    ldsm_x2t(&bhi[pb][12], Bro2H + kb);                                     \
} while (0)
#define LDBLO(kt) do {                                                      \
    u32 kb = (u32)((kt) * 16 * BP2 * 2);                                    \
    ldsm_x4t(&blo[0],  BroL + kb);                                          \
    ldsm_x4t(&blo[4],  BroL + kb + 32u);                                    \
    ldsm_x4t(&blo[8],  BroL + kb + 64u);                                    \
    ldsm_x2t(&blo[12], Bro2L + kb);                                         \
} while (0)
        LDBHI(0, 0);
#pragma unroll
        for (int kt = 0; kt < 8; ++kt) {
            int pb = kt & 1;
            LDBLO(kt);
            ldsm_x4(alo, AbL + (u32)(kt * 32));
            mma_fp16(acc[0], fahi[kt], &bhi[pb][0]);
            mma_fp16(acc[1], fahi[kt], &bhi[pb][2]);
            mma_fp16(acc[2], fahi[kt], &bhi[pb][4]);
            mma_fp16(acc[3], fahi[kt], &bhi[pb][6]);
            mma_fp16(acc[4], fahi[kt], &bhi[pb][8]);
            mma_fp16(acc[5], fahi[kt], &bhi[pb][10]);
            mma_fp16(acc[6], fahi[kt], &bhi[pb][12]);
            if (kt < 7) LDBHI(pb ^ 1, kt + 1);
            mma_fp16(acc[0], alo, &bhi[pb][0]);
            mma_fp16(acc[1], alo, &bhi[pb][2]);
            mma_fp16(acc[2], alo, &bhi[pb][4]);
            mma_fp16(acc[3], alo, &bhi[pb][6]);
            mma_fp16(acc[4], alo, &bhi[pb][8]);
            mma_fp16(acc[5], alo, &bhi[pb][10]);
            mma_fp16(acc[6], alo, &bhi[pb][12]);
            mma_fp16(acc[0], fahi[kt], &blo[0]);
            mma_fp16(acc[1], fahi[kt], &blo[2]);
            mma_fp16(acc[2], fahi[kt], &blo[4]);
            mma_fp16(acc[3], fahi[kt], &blo[6]);
            mma_fp16(acc[4], fahi[kt], &blo[8]);
            mma_fp16(acc[5], fahi[kt], &blo[10]);
            mma_fp16(acc[6], fahi[kt], &blo[12]);
        }
#undef LDBHI
#undef LDBLO
        __syncthreads();   // all warps done reading B[sb2] (freed for stage s+2)

        // D staging (valid cols < 52)
#pragma unroll
        for (int nt = 0; nt < 7; ++nt) {
            int n0s = nt * 8 + tig * 2;
            if (n0s < 52) {
                D[o_a * DP2 + n0s]     = acc[nt][0];
                D[o_a * DP2 + n0s + 1] = acc[nt][1];
                D[o_b * DP2 + n0s]     = acc[nt][2];
                D[o_b * DP2 + n0s + 1] = acc[nt][3];
            }
        }
        __syncthreads();

        // BN + ReLU + coalesced store (stage = 2 t's)
        int tb = nb * 8 + ns * 2;
        float ck = csf[bi * 32 + ((lane < JJ) ? lane : 0)];
        float* outb = out + (size_t)bb * 409600;
#pragma unroll
        for (int rr = 0; rr < 32; ++rr) {
            int idx = warp * 32 + rr;
            int o = idx >> 1, tl = idx & 1;
            float4 bn = sbn[o];
            if (lane < JJ) {
                float v = D[o * DP2 + tl * 26 + lane];
                float pre = fmaf(bn.z, ck, v);
                outb[(size_t)o * 3200 + (tb + tl) * 25 + lane] =
                    fmaxf(fmaf(pre, bn.x, bn.y), 0.f);
            }
        }
        // next iteration's post-MMA __syncthreads orders D reuse
    }
}

// ---------------- launch ----------------
extern "C" void kernel_launch(void* const* d_in, const int* in_sizes, int n_in,
                              void* d_out, int out_size) {
    const float* x     = (const float*)d_in[0];
    const float* adj   = (const float*)d_in[1];
    const float* Wk    = (const float*)d_in[2];
    const float* bk    = (const float*)d_in[3];
    const float* Wq    = (const float*)d_in[4];
    const float* bq    = (const float*)d_in[5];
    const float* Ws    = (const float*)d_in[6];
    const float* bs    = (const float*)d_in[7];
    const float* gamma = (const float*)d_in[8];
    const float* beta  = (const float*)d_in[9];
    const float* rmean = (const float*)d_in[10];
    const float* rvar  = (const float*)d_in[11];
    const float* alpha = (const float*)d_in[12];
    float* out = (float*)d_out;

    cudaFuncSetAttribute(km_mix, cudaFuncAttributeMaxDynamicSharedMemorySize, KM_SMEM);
    cudaFuncSetAttribute(kg_gemm, cudaFuncAttributeMaxDynamicSharedMemorySize, KG_SMEM);

    k1_mean<<<dim3(16, NB), 256>>>(x);
    k2_attn<<<NB, 128>>>(adj, Wk, bk, Wq, bq, alpha);
    km_mix<<<dim3(32, NB), 256, KM_SMEM>>>(x);
    kg_gemm<<<dim3(16, 8), 256, KG_SMEM>>>(Ws, bs, gamma, beta, rmean, rvar, out);
}

// round 12
// speedup vs baseline: 1.2280x; 1.2280x over previous
#include <cuda_runtime.h>
#include <cuda_fp16.h>

typedef unsigned int u32;
typedef unsigned long long u64;

#define NB 64
#define CIN 128
#define COUT 128
#define TT 128
#define JJ 25

#define TSLAB 16
#define CHT 2
#define NCHUNK 8
#define NTILES 7
#define AP 136
#define BP 56
#define RAWP 51
#define DP 57

// ---- smem byte offsets ----
#define SM_SBN   0                       // 128 float4
#define SM_CSF   2048                    // 32 floats
#define SM_E     2176                    // 25*26 floats = 2600
#define SM_A_HI  4800                    // 128*136*2 = 34816
#define SM_A_LO  39616
#define SM_B0    74432
#define B_HALF   14336
#define B_BUF    28672
#define SM_BH(b) (SM_B0 + (b)*B_BUF)
#define SM_BL(b) (SM_BH(b) + B_HALF)
#define SM_D     131776                  // 128*57*4 = 29184 (single buffer)
#define SM_RAW0  160960
#define RAW_BYTES 26112
#define SM_RAW(b) (SM_RAW0 + (b)*RAW_BYTES)
#define SMEM_TOTAL 213184

// named barrier ids
#define BAR_FULL(b) (1 + (b))
#define BAR_FREE(b) (3 + (b))
#define BAR_DFULL   5
#define BAR_DFREE   6
#define BAR_PROD    7

// ---------------- scratch ----------------
__device__ float g_xt_mean[NB * CIN * JJ];
__device__ float g_E[NB * JJ * JJ];
__device__ float g_csf[NB * JJ];

// ---------------- helpers ----------------
__device__ __forceinline__ u64 pack2(float lo, float hi) {
    u64 r; asm("mov.b64 %0, {%1,%2};" : "=l"(r) : "f"(lo), "f"(hi)); return r;
}
__device__ __forceinline__ void unpack2(u64 v, float& lo, float& hi) {
    asm("mov.b64 {%0,%1}, %2;" : "=f"(lo), "=f"(hi) : "l"(v));
}
__device__ __forceinline__ u64 ffma2(u64 a, u64 b, u64 c) {
    u64 d; asm("fma.rn.f32x2 %0, %1, %2, %3;" : "=l"(d) : "l"(a), "l"(b), "l"(c)); return d;
}
__device__ __forceinline__ u32 smem_u32(const void* p) {
    u32 a; asm("{ .reg .u64 t; cvta.to.shared.u64 t, %1; cvt.u32.u64 %0, t; }" : "=r"(a) : "l"(p));
    return a;
}
__device__ __forceinline__ void ldsm_x4(u32* r, u32 addr) {
    asm volatile("ldmatrix.sync.aligned.m8n8.x4.shared.b16 {%0,%1,%2,%3}, [%4];"
        : "=r"(r[0]), "=r"(r[1]), "=r"(r[2]), "=r"(r[3]) : "r"(addr) : "memory");
}
__device__ __forceinline__ void ldsm_x4t(u32* r, u32 addr) {
    asm volatile("ldmatrix.sync.aligned.m8n8.x4.trans.shared.b16 {%0,%1,%2,%3}, [%4];"
        : "=r"(r[0]), "=r"(r[1]), "=r"(r[2]), "=r"(r[3]) : "r"(addr) : "memory");
}
__device__ __forceinline__ void ldsm_x2t(u32* r, u32 addr) {
    asm volatile("ldmatrix.sync.aligned.m8n8.x2.trans.shared.b16 {%0,%1}, [%2];"
        : "=r"(r[0]), "=r"(r[1]) : "r"(addr) : "memory");
}
__device__ __forceinline__ void mma_fp16(float* d, const u32* a, const u32* b) {
    asm volatile("mma.sync.aligned.m16n8k16.row.col.f32.f16.f16.f32 "
        "{%0,%1,%2,%3}, {%4,%5,%6,%7}, {%8,%9}, {%0,%1,%2,%3};"
        : "+f"(d[0]), "+f"(d[1]), "+f"(d[2]), "+f"(d[3])
        : "r"(a[0]), "r"(a[1]), "r"(a[2]), "r"(a[3]), "r"(b[0]), "r"(b[1]));
}
__device__ __forceinline__ void cp4(u32 dst, const void* src) {
    asm volatile("cp.async.ca.shared.global [%0], [%1], 4;" :: "r"(dst), "l"(src) : "memory");
}
#define CP_COMMIT() asm volatile("cp.async.commit_group;" ::: "memory")
#define CP_WAIT1()  asm volatile("cp.async.wait_group 1;" ::: "memory")
#define CP_WAITALL() asm volatile("cp.async.wait_group 0;" ::: "memory")
#define BAR_SYNC(id, cnt) asm volatile("bar.sync %0, %1;" :: "r"(id), "r"(cnt) : "memory")
#define BAR_ARRIVE(id, cnt) asm volatile("bar.arrive %0, %1;" :: "r"(id), "r"(cnt) : "memory")

__device__ __forceinline__ u32 packh(float a, float b) {
    __half h0 = __float2half_rn(a), h1 = __float2half_rn(b);
    return (u32)__half_as_ushort(h0) | ((u32)__half_as_ushort(h1) << 16);
}

// ---------------- K1: temporal mean ----------------
__global__ void k1_mean(const float* __restrict__ x) {
    int b = blockIdx.y;
    int c = blockIdx.x * 8 + (threadIdx.x >> 5);
    int j = threadIdx.x & 31;
    if (j >= JJ) return;
    const float* p = x + ((size_t)(b * CIN + c) * TT) * JJ + j;
    float a0 = 0.f, a1 = 0.f, a2 = 0.f, a3 = 0.f;
    float a4 = 0.f, a5 = 0.f, a6 = 0.f, a7 = 0.f;
#pragma unroll 4
    for (int t = 0; t < TT; t += 8) {
        a0 += p[t * JJ];       a1 += p[(t + 1) * JJ];
        a2 += p[(t + 2) * JJ]; a3 += p[(t + 3) * JJ];
        a4 += p[(t + 4) * JJ]; a5 += p[(t + 5) * JJ];
        a6 += p[(t + 6) * JJ]; a7 += p[(t + 7) * JJ];
    }
    g_xt_mean[(b * CIN + c) * JJ + j] =
        ((a0 + a1) + (a2 + a3) + ((a4 + a5) + (a6 + a7))) * (1.0f / TT);
}

// ---------------- K2: per-batch attention -> E[b], csf[b] ----------------
__global__ void k2_attn(const float* __restrict__ adj,
                        const float* __restrict__ Wk, const float* __restrict__ bk,
                        const float* __restrict__ Wq, const float* __restrict__ bq,
                        const float* __restrict__ alphaPtr) {
    int b = blockIdx.x;
    int tid = threadIdx.x;  // 128
    __shared__ float xt[CIN * 26];
    __shared__ float skk[COUT * 26];
    __shared__ float sqq[COUT * 26];
    __shared__ float sdyn[JJ * 26];

    for (int i = tid; i < CIN * JJ; i += 128) {
        int c = i / JJ, j = i - c * JJ;
        xt[c * 26 + j] = g_xt_mean[b * CIN * JJ + i];
    }
    __syncthreads();
    {
        int o = tid;
        const float4* wk4 = (const float4*)(Wk + o * CIN);
        const float4* wq4 = (const float4*)(Wq + o * CIN);
        float ak[JJ], aq[JJ];
#pragma unroll
        for (int j = 0; j < JJ; j++) { ak[j] = 0.f; aq[j] = 0.f; }
#pragma unroll 4
        for (int c4 = 0; c4 < CIN / 4; ++c4) {
            float4 wk = wk4[c4], wq = wq4[c4];
            const float* x0 = &xt[(c4 * 4) * 26];
#pragma unroll
            for (int j = 0; j < JJ; j++) {
                float v0 = x0[j], v1 = x0[26 + j], v2 = x0[52 + j], v3 = x0[78 + j];
                float a = ak[j], q = aq[j];
                a = fmaf(wk.x, v0, a); q = fmaf(wq.x, v0, q);
                a = fmaf(wk.y, v1, a); q = fmaf(wq.y, v1, q);
                a = fmaf(wk.z, v2, a); q = fmaf(wq.z, v2, q);
                a = fmaf(wk.w, v3, a); q = fmaf(wq.w, v3, q);
                ak[j] = a; aq[j] = q;
            }
        }
        float bko = bk[o], bqo = bq[o];
#pragma unroll
        for (int j = 0; j < JJ; j++) { skk[o * 26 + j] = ak[j] + bko; sqq[o * 26 + j] = aq[j] + bqo; }
    }
    __syncthreads();
    const float inv_scale = 0.08838834764831843f;
    for (int i = tid; i < JJ * JJ; i += 128) {
        int j = i / JJ, k = i - j * JJ;
        float acc = 0.f;
        for (int o = 0; o < COUT; o++) acc = fmaf(sqq[o * 26 + j], skk[o * 26 + k], acc);
        sdyn[j * 26 + k] = acc * inv_scale;
    }
    __syncthreads();
    if (tid < JJ) {
        int j = tid;
        float m = -1e30f;
#pragma unroll
        for (int k = 0; k < JJ; k++) m = fmaxf(m, sdyn[j * 26 + k]);
        float e[JJ]; float s = 0.f;
#pragma unroll
        for (int k = 0; k < JJ; k++) { e[k] = expf(sdyn[j * 26 + k] - m); s += e[k]; }
        float inv = 1.0f / s;
#pragma unroll
        for (int k = 0; k < JJ; k++) sdyn[j * 26 + k] = e[k] * inv;
    }
    __syncthreads();
    float alpha = alphaPtr[0];
    for (int i = tid; i < JJ * JJ; i += 128) {
        int j = i / JJ, k = i - j * JJ;
        float acc = 0.f;
#pragma unroll
        for (int m2 = 0; m2 < JJ; m2++) acc = fmaf(adj[j * JJ + m2], sdyn[m2 * 26 + k], acc);
        g_E[b * JJ * JJ + i] = adj[j * JJ + k] + alpha * acc;
    }
    if (tid < JJ) {
        int k = tid;
        float acc = 0.f;
#pragma unroll
        for (int j = 0; j < JJ; j++) acc += sdyn[j * 26 + k];
        g_csf[b * JJ + k] = 1.0f + alpha * acc;
    }
}

// ---------------- K3 ----------------
__global__ void __launch_bounds__(512, 1)
k3_main(const float* __restrict__ x, const float* __restrict__ Ws,
        const float* __restrict__ bs, const float* __restrict__ gamma,
        const float* __restrict__ beta, const float* __restrict__ rmean,
        const float* __restrict__ rvar, float* __restrict__ out) {
    extern __shared__ char sm[];
    u32 sbase = smem_u32(sm);
    int tid = threadIdx.x;
    int b = blockIdx.y, slab = blockIdx.x;
    int t0slab = slab * TSLAB;

    bool is_prod = tid >= 256;
    int ptid = tid & 255;
    const float* xb = x + (size_t)b * 409600 + (size_t)t0slab * 25;

    // ---- producers: cp.async raw chunks 0,1 ----
    if (is_prod) {
#pragma unroll
        for (int cb = 0; cb < 2; ++cb) {
#pragma unroll
            for (int k = 0; k < 25; ++k) {
                int flat = ptid + 256 * k;
                int c = flat / 50, col = flat - 50 * c;
                cp4(sbase + SM_RAW(cb) + (u32)((c * RAWP + col) * 4),
                    xb + (size_t)c * 3200 + cb * 50 + col);
            }
            CP_COMMIT();
        }
    }

    // ---- staging (all 512 threads) ----
    float* csf = (float*)(sm + SM_CSF);
    float* Es  = (float*)(sm + SM_E);
    if (tid < 32) csf[tid] = (tid < JJ) ? g_csf[b * JJ + tid] : 0.f;
    if (tid >= 128 && tid < 256) {
        int o = tid - 128;
        float inv = gamma[o] * rsqrtf(rvar[o] + 1e-5f);
        float sh = beta[o] - rmean[o] * inv;
        ((float4*)(sm + SM_SBN))[o] = make_float4(inv, sh, bs[o], 0.f);
    }
    for (int i = tid; i < JJ * 26; i += 512) {
        int j = i / 26, k = i - 26 * j;
        Es[i] = (k < JJ) ? g_E[b * 625 + j * 25 + k] : 0.f;
    }
    {
        __half* ah = (__half*)(sm + SM_A_HI);
        __half* al = (__half*)(sm + SM_A_LO);
        for (int i = tid; i < COUT * CIN; i += 512) {
            int o = i >> 7, c = i & 127;
            float v = Ws[i];
            __half hb = __float2half_rn(v);
            ah[o * AP + c] = hb;
            al[o * AP + c] = __float2half_rn(v - __half2float(hb));
        }
    }
    __syncthreads();

    if (!is_prod) {
        // ===== CONSUMERS (warps 0..7): MMA + D-stage ONLY =====
        int warp = tid >> 5, lane = tid & 31;
        int o0 = warp * 16;
        int gid = lane >> 2, tig = lane & 3;
        u32 arow  = (u32)(o0 + (lane & 15));
        u32 acsel = (u32)((lane >> 4) * 8);
        u32 brow  = (u32)((lane & 7) + ((lane >> 3) & 1) * 8);
        u32 bcsel = (u32)((lane >> 4) * 8);
        u32 brow2 = (u32)(lane & 15);
        int o_a = o0 + gid, o_b = o_a + 8;
        float* D = (float*)(sm + SM_D);

        u32 AbH = sbase + (u32)SM_A_HI + (arow * AP + acsel) * 2;
        u32 AbL = sbase + (u32)SM_A_LO + (arow * AP + acsel) * 2;

        // persistent Ahi frags
        u32 fahi[8][4];
#pragma unroll
        for (int kt = 0; kt < 8; ++kt) ldsm_x4(fahi[kt], AbH + (u32)(kt * 32));

        for (int ch = 0; ch < NCHUNK; ++ch) {
            int cbuf = ch & 1;
            BAR_SYNC(BAR_FULL(cbuf), 512);

            u32 BbH = sbase + (u32)SM_BH(cbuf);
            u32 BbL = sbase + (u32)SM_BL(cbuf);
            u32 BroH  = BbH + (brow * BP + bcsel) * 2;
            u32 BroL  = BbL + (brow * BP + bcsel) * 2;
            u32 Bro2H = BbH + (brow2 * BP + 48u) * 2;
            u32 Bro2L = BbL + (brow2 * BP + 48u) * 2;

            float acc[NTILES][4];
#pragma unroll
            for (int nt = 0; nt < NTILES; ++nt)
#pragma unroll
                for (int r = 0; r < 4; ++r) acc[nt][r] = 0.f;

            u32 bhi[2][14], blo[14], alo[4];
#define LDBHI(pb, kt) do {                                                  \
    u32 kb = (u32)((kt) * 16 * BP * 2);                                     \
    ldsm_x4t(&bhi[pb][0],  BroH + kb);                                      \
    ldsm_x4t(&bhi[pb][4],  BroH + kb + 32u);                                \
    ldsm_x4t(&bhi[pb][8],  BroH + kb + 64u);                                \
    ldsm_x2t(&bhi[pb][12], Bro2H + kb);                                     \
} while (0)
#define LDBLO(kt) do {                                                      \
    u32 kb = (u32)((kt) * 16 * BP * 2);                                     \
    ldsm_x4t(&blo[0],  BroL + kb);                                          \
    ldsm_x4t(&blo[4],  BroL + kb + 32u);                                    \
    ldsm_x4t(&blo[8],  BroL + kb + 64u);                                    \
    ldsm_x2t(&blo[12], Bro2L + kb);                                         \
} while (0)
            LDBHI(0, 0);
#pragma unroll
            for (int kt = 0; kt < 8; ++kt) {
                int pb = kt & 1;
                LDBLO(kt);
                ldsm_x4(alo, AbL + (u32)(kt * 32));
                mma_fp16(acc[0], fahi[kt], &bhi[pb][0]);
                mma_fp16(acc[1], fahi[kt], &bhi[pb][2]);
                mma_fp16(acc[2], fahi[kt], &bhi[pb][4]);
                mma_fp16(acc[3], fahi[kt], &bhi[pb][6]);
                mma_fp16(acc[4], fahi[kt], &bhi[pb][8]);
                mma_fp16(acc[5], fahi[kt], &bhi[pb][10]);
                mma_fp16(acc[6], fahi[kt], &bhi[pb][12]);
                if (kt < 7) LDBHI(pb ^ 1, kt + 1);
                mma_fp16(acc[0], alo, &bhi[pb][0]);
                mma_fp16(acc[1], alo, &bhi[pb][2]);
                mma_fp16(acc[2], alo, &bhi[pb][4]);
                mma_fp16(acc[3], alo, &bhi[pb][6]);
                mma_fp16(acc[4], alo, &bhi[pb][8]);
                mma_fp16(acc[5], alo, &bhi[pb][10]);
                mma_fp16(acc[6], alo, &bhi[pb][12]);
                mma_fp16(acc[0], fahi[kt], &blo[0]);
                mma_fp16(acc[1], fahi[kt], &blo[2]);
                mma_fp16(acc[2], fahi[kt], &blo[4]);
                mma_fp16(acc[3], fahi[kt], &blo[6]);
                mma_fp16(acc[4], fahi[kt], &blo[8]);
                mma_fp16(acc[5], fahi[kt], &blo[10]);
                mma_fp16(acc[6], fahi[kt], &blo[12]);
            }
#undef LDBHI
#undef LDBLO
            BAR_ARRIVE(BAR_FREE(cbuf), 512);   // B[cbuf] free (BEFORE staging!)

            if (ch >= 1) BAR_SYNC(BAR_DFREE, 512);   // epilogue(ch-1) done
#pragma unroll
            for (int nt = 0; nt < NTILES; ++nt) {
                int n0 = nt * 8 + tig * 2;
                D[o_a * DP + n0]     = acc[nt][0];
                D[o_a * DP + n0 + 1] = acc[nt][1];
                D[o_b * DP + n0]     = acc[nt][2];
                D[o_b * DP + n0 + 1] = acc[nt][3];
            }
            BAR_ARRIVE(BAR_DFULL, 512);
        }
    } else {
        // ===== PRODUCERS (warps 8..15): mix + epilogue =====
        int lane = tid & 31;
        int pw = (tid >> 5) - 8;
        int c = ptid >> 1, h = ptid & 1;
        float* D = (float*)(sm + SM_D);
        const float4* sbn = (const float4*)(sm + SM_SBN);
        float ck = csf[lane & 31];
        float* outb = out + (size_t)b * 409600;

        for (int ch = 0; ch < NCHUNK; ++ch) {
            int buf = ch & 1;
            if (ch < NCHUNK - 2) { CP_WAIT1(); } else { CP_WAITALL(); }
            BAR_SYNC(BAR_PROD, 256);          // raw[buf] landed for all

            // read raw row into registers
            const float* xr = (const float*)(sm + SM_RAW(buf)) + c * RAWP + h * 25;
            float xv[JJ];
#pragma unroll
            for (int j = 0; j < JJ; ++j) xv[j] = xr[j];
            BAR_SYNC(BAR_PROD, 256);          // raw[buf] consumed

            if (ch + 2 < NCHUNK) {
#pragma unroll
                for (int k = 0; k < 25; ++k) {
                    int flat = ptid + 256 * k;
                    int cc = flat / 50, col = flat - 50 * cc;
                    cp4(sbase + SM_RAW(buf) + (u32)((cc * RAWP + col) * 4),
                        xb + (size_t)cc * 3200 + (ch + 2) * 50 + col);
                }
                CP_COMMIT();
            }

            // mix: z[k] = sum_j x[j] * E[j][k]  (E loads warp-uniform -> broadcast)
            u64 z[13];
            u64 zero = pack2(0.f, 0.f);
#pragma unroll
            for (int q = 0; q < 13; ++q) z[q] = zero;
#pragma unroll
            for (int j = 0; j < JJ; ++j) {
                u64 xp = pack2(xv[j], xv[j]);
                const u64* er = (const u64*)&Es[j * 26];
#pragma unroll
                for (int q = 0; q < 13; ++q) z[q] = ffma2(xp, er[q], z[q]);
            }

            if (ch >= 2) BAR_SYNC(BAR_FREE(buf), 512);   // B[buf] writable

            {   // split z -> fp16 hi/lo into B[buf] row c, cols h*26..h*26+25
                char* bh = sm + SM_BH(buf) + (c * BP + h * 26) * 2;
                char* bl = sm + SM_BL(buf) + (c * BP + h * 26) * 2;
#pragma unroll
                for (int q = 0; q < 13; ++q) {
                    float f0, f1; unpack2(z[q], f0, f1);
                    __half h0 = __float2half_rn(f0), h1 = __float2half_rn(f1);
                    *(u32*)(bh + 4 * q) = (u32)__half_as_ushort(h0) | ((u32)__half_as_ushort(h1) << 16);
                    *(u32*)(bl + 4 * q) = packh(f0 - __half2float(h0), f1 - __half2float(h1));
                }
            }
            BAR_ARRIVE(BAR_FULL(buf), 512);

            // epilogue of previous chunk (overlaps consumer MMA of this chunk)
            if (ch >= 1) {
                BAR_SYNC(BAR_DFULL, 512);
                int tch = t0slab + (ch - 1) * CHT;
#pragma unroll
                for (int rr = 0; rr < 32; ++rr) {
                    int idx = pw * 32 + rr;
                    int o = idx >> 1, tl = idx & 1;
                    float4 bn = sbn[o];
                    if (lane < JJ) {
                        float v = D[o * DP + tl * 26 + lane];
                        float pre = fmaf(bn.z, ck, v);
                        outb[(size_t)o * 3200 + (tch + tl) * 25 + lane] =
                            fmaxf(fmaf(pre, bn.x, bn.y), 0.f);
                    }
                }
                BAR_ARRIVE(BAR_DFREE, 512);
            }
        }
        // final epilogue (chunk NCHUNK-1)
        BAR_SYNC(BAR_DFULL, 512);
        {
            int tch = t0slab + (NCHUNK - 1) * CHT;
#pragma unroll
            for (int rr = 0; rr < 32; ++rr) {
                int idx = pw * 32 + rr;
                int o = idx >> 1, tl = idx & 1;
                float4 bn = sbn[o];
                if (lane < JJ) {
                    float v = D[o * DP + tl * 26 + lane];
                    float pre = fmaf(bn.z, ck, v);
                    outb[(size_t)o * 3200 + (tch + tl) * 25 + lane] =
                        fmaxf(fmaf(pre, bn.x, bn.y), 0.f);
                }
            }
        }
    }
}

// ---------------- launch ----------------
extern "C" void kernel_launch(void* const* d_in, const int* in_sizes, int n_in,
                              void* d_out, int out_size) {
    const float* x     = (const float*)d_in[0];
    const float* adj   = (const float*)d_in[1];
    const float* Wk    = (const float*)d_in[2];
    const float* bk    = (const float*)d_in[3];
    const float* Wq    = (const float*)d_in[4];
    const float* bq    = (const float*)d_in[5];
    const float* Ws    = (const float*)d_in[6];
    const float* bs    = (const float*)d_in[7];
    const float* gamma = (const float*)d_in[8];
    const float* beta  = (const float*)d_in[9];
    const float* rmean = (const float*)d_in[10];
    const float* rvar  = (const float*)d_in[11];
    const float* alpha = (const float*)d_in[12];
    float* out = (float*)d_out;

    cudaFuncSetAttribute(k3_main, cudaFuncAttributeMaxDynamicSharedMemorySize, SMEM_TOTAL);

    k1_mean<<<dim3(16, NB), 256>>>(x);
    k2_attn<<<NB, 128>>>(adj, Wk, bk, Wq, bq, alpha);
    k3_main<<<dim3(TT / TSLAB, NB), 512, SMEM_TOTAL>>>(x, Ws, bs, gamma, beta, rmean, rvar, out);
}